// round 9
// baseline (speedup 1.0000x reference)
#include <cuda_runtime.h>
#include <mma.h>
#include <cstdint>

using namespace nvcuda;

#define B_   256
#define K_   256
#define C_   128
#define KG_  64
#define OUTC 117
#define OCH  183

// scratch (allocation-free rule: __device__ globals)
__device__ float g_net1[B_ * C_ * K_];   // pre-BN layer1 output (B,128,256)
__device__ float g_net2[B_ * C_ * K_];   // pre-BN layer2 output
__device__ float g_t[B_ * OUTC * K_];    // layer3 output (B,117,256)
__device__ float g_s[2][C_];             // BN sum accumulators
__device__ float g_s2[2][C_];            // BN sum-of-squares accumulators
__device__ float g_a[2][C_], g_d[2][C_]; // folded BN scale/shift

// ===========================================================================
// prep: objectness_label + get_index + zero BN accumulators (fused)
// ===========================================================================
__global__ void prep_kernel(const float* __restrict__ xyz,
                            const float* __restrict__ gt,
                            const int* __restrict__ pred,
                            float* __restrict__ lbl,
                            float* __restrict__ idxo,
                            float* __restrict__ sum1) {
    int b = blockIdx.x, k = threadIdx.x;
    if (b == 0 && k < C_) {
        g_s[0][k] = 0.f; g_s[1][k] = 0.f;
        g_s2[0][k] = 0.f; g_s2[1][k] = 0.f;
    }
    __shared__ float sg[KG_ * 3];
    if (k < KG_ * 3) sg[k] = gt[b * KG_ * 3 + k];
    __syncthreads();
    const float* p = xyz + (b * K_ + k) * 3;
    float x = p[0], y = p[1], z = p[2];
    float mn = 1e30f;
#pragma unroll 8
    for (int g = 0; g < KG_; g++) {
        float dx = x - sg[g * 3 + 0];
        float dy = y - sg[g * 3 + 1];
        float dz = z - sg[g * 3 + 2];
        mn = fminf(mn, dx * dx + dy * dy + dz * dz);
    }
    lbl[b * K_ + k] = (sqrtf(mn + 1e-6f) < 0.3f) ? 1.0f : 0.0f;

    int pv = pred[b * K_ + k];
    __shared__ int sc[K_];
    __shared__ int res[K_];
    sc[k] = pv;
    res[k] = k;
    __syncthreads();
    for (int off = 1; off < K_; off <<= 1) {
        int add = (k >= off) ? sc[k - off] : 0;
        __syncthreads();
        sc[k] += add;
        __syncthreads();
    }
    int num = sc[K_ - 1];
    int excl = sc[k] - pv;
    if (pv == 1) res[excl] = k;
    __syncthreads();
    idxo[b * K_ + k] = (float)((k < num) ? res[k] : k);
    if (k == 0) sum1[b] = (float)num;
}

// ===========================================================================
// wmma tf32 GEMM: Y[b,m,n] = sum_c W[m,c] * X[b,c,n] + bias[m]
// grid = (2 n-halves, B_), 256 threads (8 warps), CTA tile 128x128,
// warp tile 32x64 (2x4 frags), K chunked by 64, 2 CTAs per SM.
// MODE 0: X = concat(X0,X1) along c.  MODE 1: X = relu(X0*a[c]+d[c]).
// STATS : fused per-channel sum/sum^2 via shfl + atomics.
// ===========================================================================
#define ALD 68     // As leading dim (floats): 128 rows x 64 k
#define BLD 132    // Bs leading dim: 64 k x 128 n
#define DLD 132    // D staging leading dim
#define SMEM_FLOATS (C_ * ALD + 64 * BLD)   // 8704 + 8448 = 17152 (68.6 KB)

template <int CIN, int MODE, int STATS>
__global__ void __launch_bounds__(256, 2)
wmma_gemm(const float* __restrict__ W, const float* __restrict__ bias,
          const float* __restrict__ X0, const float* __restrict__ X1,
          const float* __restrict__ aa, const float* __restrict__ dd,
          float* __restrict__ Y, int M,
          float* __restrict__ sS, float* __restrict__ sS2) {
    extern __shared__ float smbuf[];
    float* As = smbuf;                 // [128][ALD]
    float* Bs = smbuf + C_ * ALD;      // [64][BLD]
    float* Dsm = smbuf;                // reused post-mainloop [128][DLD]

    int tid = threadIdx.x;
    int w = tid >> 5;
    int b = blockIdx.y;
    int n0 = blockIdx.x * 128;

    int mw = w >> 1;      // 0..3 -> m offset mw*32
    int nw = w & 1;       // 0..1 -> n offset nw*64

    wmma::fragment<wmma::accumulator, 16, 16, 8, float> acc[2][4];
#pragma unroll
    for (int i = 0; i < 2; i++)
#pragma unroll
        for (int j = 0; j < 4; j++)
            wmma::fill_fragment(acc[i][j], 0.f);

    // staging maps
    int arow = tid >> 1, ahalf = (tid & 1) * 32;   // A: 128 rows x 64 (2 thr/row)
    int brow = tid >> 2, bq = (tid & 3) * 32;      // B: 64 rows x 128 (4 thr/row)

    const float* xb0 = X0 + b * C_ * K_ + n0;
    const float* xb1 = (MODE == 0) ? X1 + b * C_ * K_ + n0 : nullptr;

    for (int c0 = 0; c0 < CIN; c0 += 64) {
        if (c0) __syncthreads();   // protect smem reuse after prior compute
        // ---- stage A: W[arow, c0+ahalf .. +32) -> As (tf32-rounded) ----
        {
            float* dst = As + arow * ALD + ahalf;
            if (arow < M) {
                const float* wp = W + arow * CIN + c0 + ahalf;
#pragma unroll
                for (int q = 0; q < 8; q++) {
                    float4 v = *reinterpret_cast<const float4*>(wp + q * 4);
                    dst[q * 4 + 0] = wmma::__float_to_tf32(v.x);
                    dst[q * 4 + 1] = wmma::__float_to_tf32(v.y);
                    dst[q * 4 + 2] = wmma::__float_to_tf32(v.z);
                    dst[q * 4 + 3] = wmma::__float_to_tf32(v.w);
                }
            } else {
#pragma unroll
                for (int q = 0; q < 32; q++) dst[q] = 0.f;
            }
        }
        // ---- stage B: X[c0+brow, n0+bq .. +32) -> Bs (BN/relu + tf32) ----
        {
            int cg = c0 + brow;
            const float* xp;
            if (MODE == 0)
                xp = (cg < C_) ? xb0 + cg * K_ : xb1 + (cg - C_) * K_;
            else
                xp = xb0 + cg * K_;
            float av = 0.f, dv = 0.f;
            if (MODE == 1) { av = __ldg(aa + cg); dv = __ldg(dd + cg); }
            float* dst = Bs + brow * BLD + bq;
#pragma unroll
            for (int q = 0; q < 8; q++) {
                float4 v = *reinterpret_cast<const float4*>(xp + bq + q * 4);
                if (MODE == 1) {
                    v.x = fmaxf(fmaf(v.x, av, dv), 0.f);
                    v.y = fmaxf(fmaf(v.y, av, dv), 0.f);
                    v.z = fmaxf(fmaf(v.z, av, dv), 0.f);
                    v.w = fmaxf(fmaf(v.w, av, dv), 0.f);
                }
                dst[q * 4 + 0] = wmma::__float_to_tf32(v.x);
                dst[q * 4 + 1] = wmma::__float_to_tf32(v.y);
                dst[q * 4 + 2] = wmma::__float_to_tf32(v.z);
                dst[q * 4 + 3] = wmma::__float_to_tf32(v.w);
            }
        }
        __syncthreads();

#pragma unroll
        for (int ks = 0; ks < 8; ks++) {
            wmma::fragment<wmma::matrix_a, 16, 16, 8, wmma::precision::tf32,
                           wmma::row_major> af[2];
            wmma::fragment<wmma::matrix_b, 16, 16, 8, wmma::precision::tf32,
                           wmma::row_major> bf[4];
#pragma unroll
            for (int i = 0; i < 2; i++)
                wmma::load_matrix_sync(af[i],
                    As + (mw * 32 + i * 16) * ALD + ks * 8, ALD);
#pragma unroll
            for (int j = 0; j < 4; j++)
                wmma::load_matrix_sync(bf[j],
                    Bs + ks * 8 * BLD + nw * 64 + j * 16, BLD);
#pragma unroll
            for (int i = 0; i < 2; i++)
#pragma unroll
                for (int j = 0; j < 4; j++)
                    wmma::mma_sync(acc[i][j], af[i], bf[j], acc[i][j]);
        }
    }
    __syncthreads();

    // ---- epilogue: single wave through smem; bias + stats + store ----
#pragma unroll
    for (int i = 0; i < 2; i++)
#pragma unroll
        for (int j = 0; j < 4; j++)
            wmma::store_matrix_sync(
                Dsm + (mw * 32 + i * 16) * DLD + nw * 64 + j * 16,
                acc[i][j], DLD, wmma::mem_row_major);
    __syncthreads();

    int erow = tid >> 1;                 // 0..127
    int eoff = (tid & 1) * 64;
    float s = 0.f, s2 = 0.f;
    if (erow < M) {
        float bb = __ldg(bias + erow);
        float* yp = Y + b * M * K_ + erow * K_ + n0 + eoff;
        const float* sp = Dsm + erow * DLD + eoff;
#pragma unroll
        for (int q = 0; q < 16; q++) {
            float4 v = *reinterpret_cast<const float4*>(sp + q * 4);
            v.x += bb; v.y += bb; v.z += bb; v.w += bb;
            *reinterpret_cast<float4*>(yp + q * 4) = v;
            if (STATS) {
                s += v.x + v.y + v.z + v.w;
                s2 = fmaf(v.x, v.x, s2); s2 = fmaf(v.y, v.y, s2);
                s2 = fmaf(v.z, v.z, s2); s2 = fmaf(v.w, v.w, s2);
            }
        }
    }
    if (STATS) {
        s  += __shfl_xor_sync(0xffffffffu, s, 1);
        s2 += __shfl_xor_sync(0xffffffffu, s2, 1);
        if ((tid & 1) == 0 && erow < M) {
            atomicAdd(&sS[erow], s);
            atomicAdd(&sS2[erow], s2);
        }
    }
}

// ===========================================================================
// finalize BN fold: relu_bn(x) = relu(x*a + d)
// ===========================================================================
__global__ void finalize_kernel(const float* __restrict__ g,
                                const float* __restrict__ be,
                                const float* __restrict__ sS,
                                const float* __restrict__ sS2,
                                float* __restrict__ a, float* __restrict__ d) {
    int c = threadIdx.x;
    if (c < C_) {
        const float invN = 1.0f / (B_ * K_);
        float mean = sS[c] * invN;
        float var = sS2[c] * invN - mean * mean;
        float rstd = rsqrtf(var + 1e-5f);
        float av = rstd * g[c];
        a[c] = av;
        d[c] = be[c] - mean * av;
    }
}

// ===========================================================================
// Assemble the 183-channel output (SMEM transpose, coalesced both ways)
// ===========================================================================
__global__ void epilogue_kernel(const float* __restrict__ xyz,
                                const float* __restrict__ ms,
                                float* __restrict__ out) {
    __shared__ float s[OUTC * 65];
    __shared__ float sms[54];
    int tid = threadIdx.x;
    int k0 = blockIdx.x * 64;
    int b = blockIdx.y;

    if (tid < 54) sms[tid] = ms[tid];
    const float* tp = g_t + b * OUTC * K_ + k0;
    for (int e = tid; e < OUTC * 64; e += 256) {
        int o = e >> 6, k = e & 63;
        s[o * 65 + k] = tp[o * K_ + k];
    }
    __syncthreads();

    float* op = out + (b * K_ + k0) * OCH;
    for (int e = tid; e < 64 * OCH; e += 256) {
        int k = e / OCH;
        int ch = e - k * OCH;
        int o;
        float scale = 1.f, add = 0.f;
        if (ch < 27) {
            o = ch;
            if (ch < 3) add = xyz[(b * K_ + k0 + k) * 3 + ch];
        } else if (ch < 39) {
            o = ch - 12;
            scale = 0.26179938779914943f;
        } else if (ch < 111) {
            o = ch - 12;
        } else if (ch < 165) {
            o = ch - 66;
            scale = sms[ch - 111];
        } else {
            o = ch - 66;
        }
        op[e] = s[o * 65 + k] * scale + add;
    }
}

// ===========================================================================
extern "C" void kernel_launch(void* const* d_in, const int* in_sizes, int n_in,
                              void* d_out, int out_size) {
    (void)in_sizes; (void)n_in; (void)out_size;
    const float* xyz      = (const float*)d_in[0];
    const float* features = (const float*)d_in[1];
    const float* rn       = (const float*)d_in[2];
    const float* gt       = (const float*)d_in[3];
    const int*   pred     = (const int*)d_in[4];   // int32
    const float* W1 = (const float*)d_in[5];
    const float* b1 = (const float*)d_in[6];
    const float* g1 = (const float*)d_in[7];
    const float* be1 = (const float*)d_in[8];
    const float* W2 = (const float*)d_in[9];
    const float* b2 = (const float*)d_in[10];
    const float* g2 = (const float*)d_in[11];
    const float* be2 = (const float*)d_in[12];
    const float* W3 = (const float*)d_in[13];
    const float* b3 = (const float*)d_in[14];
    const float* ms = (const float*)d_in[15];
    float* out = (float*)d_out;

    const int OFF_IDX = B_ * K_ * OCH;
    const int OFF_SUM = OFF_IDX + B_ * K_;
    const int OFF_LBL = OFF_SUM + B_;

    float *p_net1, *p_net2, *p_t, *p_s, *p_s2, *p_a, *p_d;
    cudaGetSymbolAddress((void**)&p_net1, g_net1);
    cudaGetSymbolAddress((void**)&p_net2, g_net2);
    cudaGetSymbolAddress((void**)&p_t,    g_t);
    cudaGetSymbolAddress((void**)&p_s,    g_s);
    cudaGetSymbolAddress((void**)&p_s2,   g_s2);
    cudaGetSymbolAddress((void**)&p_a,    g_a);
    cudaGetSymbolAddress((void**)&p_d,    g_d);

    const int smem_bytes = SMEM_FLOATS * 4;   // 68608
    cudaFuncSetAttribute(wmma_gemm<256, 0, 1>,
                         cudaFuncAttributeMaxDynamicSharedMemorySize, smem_bytes);
    cudaFuncSetAttribute(wmma_gemm<128, 1, 1>,
                         cudaFuncAttributeMaxDynamicSharedMemorySize, smem_bytes);
    cudaFuncSetAttribute(wmma_gemm<128, 1, 0>,
                         cudaFuncAttributeMaxDynamicSharedMemorySize, smem_bytes);

    prep_kernel<<<B_, K_>>>(xyz, gt, pred,
                            out + OFF_LBL, out + OFF_IDX, out + OFF_SUM);

    dim3 gg(2, B_);
    wmma_gemm<256, 0, 1><<<gg, 256, smem_bytes>>>(W1, b1, features, rn,
                                                  nullptr, nullptr,
                                                  p_net1, C_, p_s, p_s2);
    finalize_kernel<<<1, 128>>>(g1, be1, p_s, p_s2, p_a, p_d);
    wmma_gemm<128, 1, 1><<<gg, 256, smem_bytes>>>(W2, b2, p_net1, nullptr,
                                                  p_a, p_d,
                                                  p_net2, C_, p_s + C_, p_s2 + C_);
    finalize_kernel<<<1, 128>>>(g2, be2, p_s + C_, p_s2 + C_, p_a + C_, p_d + C_);
    wmma_gemm<128, 1, 0><<<gg, 256, smem_bytes>>>(W3, b3, p_net2, nullptr,
                                                  p_a + C_, p_d + C_,
                                                  p_t, OUTC, nullptr, nullptr);

    epilogue_kernel<<<dim3(K_ / 64, B_), 256>>>(xyz, ms, out);
}

// round 10
// speedup vs baseline: 2.3058x; 2.3058x over previous
#include <cuda_runtime.h>
#include <cuda_fp16.h>
#include <mma.h>
#include <cstdint>

using namespace nvcuda;

#define B_   256
#define K_   256
#define C_   128
#define KG_  64
#define OUTC 117
#define OCH  183

// scratch (allocation-free rule: __device__ globals)
__device__ float g_net1[B_ * C_ * K_];   // pre-BN layer1 output (B,128,256)
__device__ float g_net2[B_ * C_ * K_];   // pre-BN layer2 output
__device__ float g_t[B_ * OUTC * K_];    // layer3 output (B,117,256)
__device__ float g_s[2][C_];             // BN sum accumulators
__device__ float g_s2[2][C_];            // BN sum-of-squares accumulators
__device__ float g_a[2][C_], g_d[2][C_]; // folded BN scale/shift

// ===========================================================================
// prep: objectness_label + get_index + zero BN accumulators (fused)
// ===========================================================================
__global__ void prep_kernel(const float* __restrict__ xyz,
                            const float* __restrict__ gt,
                            const int* __restrict__ pred,
                            float* __restrict__ lbl,
                            float* __restrict__ idxo,
                            float* __restrict__ sum1) {
    int b = blockIdx.x, k = threadIdx.x;
    if (b == 0 && k < C_) {
        g_s[0][k] = 0.f; g_s[1][k] = 0.f;
        g_s2[0][k] = 0.f; g_s2[1][k] = 0.f;
    }
    __shared__ float sg[KG_ * 3];
    if (k < KG_ * 3) sg[k] = gt[b * KG_ * 3 + k];
    __syncthreads();
    const float* p = xyz + (b * K_ + k) * 3;
    float x = p[0], y = p[1], z = p[2];
    float mn = 1e30f;
#pragma unroll 8
    for (int g = 0; g < KG_; g++) {
        float dx = x - sg[g * 3 + 0];
        float dy = y - sg[g * 3 + 1];
        float dz = z - sg[g * 3 + 2];
        mn = fminf(mn, dx * dx + dy * dy + dz * dz);
    }
    lbl[b * K_ + k] = (sqrtf(mn + 1e-6f) < 0.3f) ? 1.0f : 0.0f;

    int pv = pred[b * K_ + k];
    __shared__ int sc[K_];
    __shared__ int res[K_];
    sc[k] = pv;
    res[k] = k;
    __syncthreads();
    for (int off = 1; off < K_; off <<= 1) {
        int add = (k >= off) ? sc[k - off] : 0;
        __syncthreads();
        sc[k] += add;
        __syncthreads();
    }
    int num = sc[K_ - 1];
    int excl = sc[k] - pv;
    if (pv == 1) res[excl] = k;
    __syncthreads();
    idxo[b * K_ + k] = (float)((k < num) ? res[k] : k);
    if (k == 0) sum1[b] = (float)num;
}

// ===========================================================================
// wmma fp16 GEMM (fp32 accumulate): Y[b,m,n] = sum_c W[m,c]*X[b,c,n] + bias[m]
// grid = (2 n-halves, B_), 256 threads (8 warps), CTA tile 128x128,
// warp tile 32x64 (2x4 frags of 16x16x16), K chunked by 64, 2 CTA/SM.
// MODE 0: X = concat(X0,X1) along c.  MODE 1: X = relu(X0*a[c]+d[c]).
// STATS : fused per-channel sum/sum^2 via shfl + atomics.
// ===========================================================================
#define ALDH 80    // As leading dim in halves (160B rows, 16B-aligned)
#define BLDH 136   // Bs leading dim in halves (272B rows, 16B-aligned)
#define DLD  68    // D staging leading dim (floats)
// smem: As 128*80*2 = 20480 B, Bs 64*136*2 = 17408 B -> 37888 B
//       Dsm reuse: 128*68*4 = 34816 B  (fits)
#define SMEM_BYTES 37888

template <int CIN, int MODE, int STATS>
__global__ void __launch_bounds__(256, 2)
wmma_gemm(const float* __restrict__ W, const float* __restrict__ bias,
          const float* __restrict__ X0, const float* __restrict__ X1,
          const float* __restrict__ aa, const float* __restrict__ dd,
          float* __restrict__ Y, int M,
          float* __restrict__ sS, float* __restrict__ sS2) {
    __shared__ __align__(16) char smbuf[SMEM_BYTES];
    __half* Ash = reinterpret_cast<__half*>(smbuf);                 // [128][ALDH]
    __half* Bsh = reinterpret_cast<__half*>(smbuf + 20480);         // [64][BLDH]
    float*  Dsm = reinterpret_cast<float*>(smbuf);                  // reused [128][DLD]

    int tid = threadIdx.x;
    int w = tid >> 5;
    int b = blockIdx.y;
    int n0 = blockIdx.x * 128;

    int mw = w >> 1;      // 0..3 -> m offset mw*32
    int nw = w & 1;       // 0..1 -> n offset nw*64

    wmma::fragment<wmma::accumulator, 16, 16, 16, float> acc[2][4];
#pragma unroll
    for (int i = 0; i < 2; i++)
#pragma unroll
        for (int j = 0; j < 4; j++)
            wmma::fill_fragment(acc[i][j], 0.f);

    // staging maps
    int arow = tid >> 1, ahalf = (tid & 1) * 32;   // A: 128 rows x 64 (2 thr/row)
    int brow = tid >> 2, bq = (tid & 3) * 32;      // B: 64 rows x 128 (4 thr/row)

    const float* xb0 = X0 + b * C_ * K_ + n0;
    const float* xb1 = (MODE == 0) ? X1 + b * C_ * K_ + n0 : nullptr;

    for (int c0 = 0; c0 < CIN; c0 += 64) {
        if (c0) __syncthreads();   // protect smem reuse after prior compute
        // ---- stage A: W[arow, c0+ahalf .. +32) -> Ash (fp16) ----
        {
            __half* dst = Ash + arow * ALDH + ahalf;
            if (arow < M) {
                const float* wp = W + arow * CIN + c0 + ahalf;
#pragma unroll
                for (int q = 0; q < 8; q++) {
                    float4 v = *reinterpret_cast<const float4*>(wp + q * 4);
                    __half2 h0 = __floats2half2_rn(v.x, v.y);
                    __half2 h1 = __floats2half2_rn(v.z, v.w);
                    *reinterpret_cast<__half2*>(dst + q * 4)     = h0;
                    *reinterpret_cast<__half2*>(dst + q * 4 + 2) = h1;
                }
            } else {
                __half2 z = __floats2half2_rn(0.f, 0.f);
#pragma unroll
                for (int q = 0; q < 16; q++)
                    *reinterpret_cast<__half2*>(dst + q * 2) = z;
            }
        }
        // ---- stage B: X[c0+brow, n0+bq .. +32) -> Bsh (BN/relu + fp16) ----
        {
            int cg = c0 + brow;
            const float* xp;
            if (MODE == 0)
                xp = (cg < C_) ? xb0 + cg * K_ : xb1 + (cg - C_) * K_;
            else
                xp = xb0 + cg * K_;
            float av = 0.f, dv = 0.f;
            if (MODE == 1) { av = __ldg(aa + cg); dv = __ldg(dd + cg); }
            __half* dst = Bsh + brow * BLDH + bq;
#pragma unroll
            for (int q = 0; q < 8; q++) {
                float4 v = *reinterpret_cast<const float4*>(xp + bq + q * 4);
                if (MODE == 1) {
                    v.x = fmaxf(fmaf(v.x, av, dv), 0.f);
                    v.y = fmaxf(fmaf(v.y, av, dv), 0.f);
                    v.z = fmaxf(fmaf(v.z, av, dv), 0.f);
                    v.w = fmaxf(fmaf(v.w, av, dv), 0.f);
                }
                __half2 h0 = __floats2half2_rn(v.x, v.y);
                __half2 h1 = __floats2half2_rn(v.z, v.w);
                *reinterpret_cast<__half2*>(dst + q * 4)     = h0;
                *reinterpret_cast<__half2*>(dst + q * 4 + 2) = h1;
            }
        }
        __syncthreads();

#pragma unroll
        for (int ks = 0; ks < 4; ks++) {
            wmma::fragment<wmma::matrix_a, 16, 16, 16, __half,
                           wmma::row_major> af[2];
            wmma::fragment<wmma::matrix_b, 16, 16, 16, __half,
                           wmma::row_major> bf[4];
#pragma unroll
            for (int i = 0; i < 2; i++)
                wmma::load_matrix_sync(af[i],
                    Ash + (mw * 32 + i * 16) * ALDH + ks * 16, ALDH);
#pragma unroll
            for (int j = 0; j < 4; j++)
                wmma::load_matrix_sync(bf[j],
                    Bsh + ks * 16 * BLDH + nw * 64 + j * 16, BLDH);
#pragma unroll
            for (int i = 0; i < 2; i++)
#pragma unroll
                for (int j = 0; j < 4; j++)
                    wmma::mma_sync(acc[i][j], af[i], bf[j], acc[i][j]);
        }
    }
    __syncthreads();

    // ---- epilogue: two n-waves through smem; bias + stats + store ----
    int erow = tid >> 1;                 // 0..127
    int eoff = (tid & 1) * 32;
    float bb = (erow < M) ? __ldg(bias + erow) : 0.f;
    float s = 0.f, s2 = 0.f;

#pragma unroll
    for (int wave = 0; wave < 2; wave++) {
        if (nw == wave) {
#pragma unroll
            for (int i = 0; i < 2; i++)
#pragma unroll
                for (int j = 0; j < 4; j++)
                    wmma::store_matrix_sync(
                        Dsm + (mw * 32 + i * 16) * DLD + j * 16,
                        acc[i][j], DLD, wmma::mem_row_major);
        }
        __syncthreads();
        if (erow < M) {
            float* yp = Y + b * M * K_ + erow * K_ + n0 + wave * 64 + eoff;
            const float* sp = Dsm + erow * DLD + eoff;
#pragma unroll
            for (int q = 0; q < 8; q++) {
                float4 v = *reinterpret_cast<const float4*>(sp + q * 4);
                v.x += bb; v.y += bb; v.z += bb; v.w += bb;
                *reinterpret_cast<float4*>(yp + q * 4) = v;
                if (STATS) {
                    s += v.x + v.y + v.z + v.w;
                    s2 = fmaf(v.x, v.x, s2); s2 = fmaf(v.y, v.y, s2);
                    s2 = fmaf(v.z, v.z, s2); s2 = fmaf(v.w, v.w, s2);
                }
            }
        }
        __syncthreads();
    }

    if (STATS && erow < M) {
        s  += __shfl_xor_sync(0xffffffffu, s, 1);
        s2 += __shfl_xor_sync(0xffffffffu, s2, 1);
        if ((tid & 1) == 0) {
            atomicAdd(&sS[erow], s);
            atomicAdd(&sS2[erow], s2);
        }
    }
}

// ===========================================================================
// finalize BN fold: relu_bn(x) = relu(x*a + d)
// ===========================================================================
__global__ void finalize_kernel(const float* __restrict__ g,
                                const float* __restrict__ be,
                                const float* __restrict__ sS,
                                const float* __restrict__ sS2,
                                float* __restrict__ a, float* __restrict__ d) {
    int c = threadIdx.x;
    if (c < C_) {
        const float invN = 1.0f / (B_ * K_);
        float mean = sS[c] * invN;
        float var = sS2[c] * invN - mean * mean;
        float rstd = rsqrtf(var + 1e-5f);
        float av = rstd * g[c];
        a[c] = av;
        d[c] = be[c] - mean * av;
    }
}

// ===========================================================================
// Assemble the 183-channel output (SMEM transpose, coalesced both ways)
// ===========================================================================
__global__ void epilogue_kernel(const float* __restrict__ xyz,
                                const float* __restrict__ ms,
                                float* __restrict__ out) {
    __shared__ float s[OUTC * 65];
    __shared__ float sms[54];
    int tid = threadIdx.x;
    int k0 = blockIdx.x * 64;
    int b = blockIdx.y;

    if (tid < 54) sms[tid] = ms[tid];
    const float* tp = g_t + b * OUTC * K_ + k0;
    for (int e = tid; e < OUTC * 64; e += 256) {
        int o = e >> 6, k = e & 63;
        s[o * 65 + k] = tp[o * K_ + k];
    }
    __syncthreads();

    float* op = out + (b * K_ + k0) * OCH;
    for (int e = tid; e < 64 * OCH; e += 256) {
        int k = e / OCH;
        int ch = e - k * OCH;
        int o;
        float scale = 1.f, add = 0.f;
        if (ch < 27) {
            o = ch;
            if (ch < 3) add = xyz[(b * K_ + k0 + k) * 3 + ch];
        } else if (ch < 39) {
            o = ch - 12;
            scale = 0.26179938779914943f;
        } else if (ch < 111) {
            o = ch - 12;
        } else if (ch < 165) {
            o = ch - 66;
            scale = sms[ch - 111];
        } else {
            o = ch - 66;
        }
        op[e] = s[o * 65 + k] * scale + add;
    }
}

// ===========================================================================
extern "C" void kernel_launch(void* const* d_in, const int* in_sizes, int n_in,
                              void* d_out, int out_size) {
    (void)in_sizes; (void)n_in; (void)out_size;
    const float* xyz      = (const float*)d_in[0];
    const float* features = (const float*)d_in[1];
    const float* rn       = (const float*)d_in[2];
    const float* gt       = (const float*)d_in[3];
    const int*   pred     = (const int*)d_in[4];   // int32
    const float* W1 = (const float*)d_in[5];
    const float* b1 = (const float*)d_in[6];
    const float* g1 = (const float*)d_in[7];
    const float* be1 = (const float*)d_in[8];
    const float* W2 = (const float*)d_in[9];
    const float* b2 = (const float*)d_in[10];
    const float* g2 = (const float*)d_in[11];
    const float* be2 = (const float*)d_in[12];
    const float* W3 = (const float*)d_in[13];
    const float* b3 = (const float*)d_in[14];
    const float* ms = (const float*)d_in[15];
    float* out = (float*)d_out;

    const int OFF_IDX = B_ * K_ * OCH;
    const int OFF_SUM = OFF_IDX + B_ * K_;
    const int OFF_LBL = OFF_SUM + B_;

    float *p_net1, *p_net2, *p_t, *p_s, *p_s2, *p_a, *p_d;
    cudaGetSymbolAddress((void**)&p_net1, g_net1);
    cudaGetSymbolAddress((void**)&p_net2, g_net2);
    cudaGetSymbolAddress((void**)&p_t,    g_t);
    cudaGetSymbolAddress((void**)&p_s,    g_s);
    cudaGetSymbolAddress((void**)&p_s2,   g_s2);
    cudaGetSymbolAddress((void**)&p_a,    g_a);
    cudaGetSymbolAddress((void**)&p_d,    g_d);

    prep_kernel<<<B_, K_>>>(xyz, gt, pred,
                            out + OFF_LBL, out + OFF_IDX, out + OFF_SUM);

    dim3 gg(2, B_);
    wmma_gemm<256, 0, 1><<<gg, 256>>>(W1, b1, features, rn, nullptr, nullptr,
                                      p_net1, C_, p_s, p_s2);
    finalize_kernel<<<1, 128>>>(g1, be1, p_s, p_s2, p_a, p_d);
    wmma_gemm<128, 1, 1><<<gg, 256>>>(W2, b2, p_net1, nullptr, p_a, p_d,
                                      p_net2, C_, p_s + C_, p_s2 + C_);
    finalize_kernel<<<1, 128>>>(g2, be2, p_s + C_, p_s2 + C_, p_a + C_, p_d + C_);
    wmma_gemm<128, 1, 0><<<gg, 256>>>(W3, b3, p_net2, nullptr, p_a + C_, p_d + C_,
                                      p_t, OUTC, nullptr, nullptr);

    epilogue_kernel<<<dim3(K_ / 64, B_), 256>>>(xyz, ms, out);
}

// round 11
// speedup vs baseline: 2.3111x; 1.0023x over previous
#include <cuda_runtime.h>
#include <cuda_fp16.h>
#include <mma.h>
#include <cstdint>

using namespace nvcuda;

#define B_   256
#define K_   256
#define C_   128
#define KG_  64
#define OUTC 117
#define OCH  183

// scratch (allocation-free rule: __device__ globals)
__device__ float g_net1[B_ * C_ * K_];   // pre-BN layer1 output (B,128,256)
__device__ float g_net2[B_ * C_ * K_];   // pre-BN layer2 output
__device__ float g_s[2][C_];             // BN sum accumulators
__device__ float g_s2[2][C_];            // BN sum-of-squares accumulators
__device__ float g_a[2][C_], g_d[2][C_]; // folded BN scale/shift

// ===========================================================================
// prep: objectness_label + get_index + zero BN accumulators (fused)
// ===========================================================================
__global__ void prep_kernel(const float* __restrict__ xyz,
                            const float* __restrict__ gt,
                            const int* __restrict__ pred,
                            float* __restrict__ lbl,
                            float* __restrict__ idxo,
                            float* __restrict__ sum1) {
    int b = blockIdx.x, k = threadIdx.x;
    if (b == 0 && k < C_) {
        g_s[0][k] = 0.f; g_s[1][k] = 0.f;
        g_s2[0][k] = 0.f; g_s2[1][k] = 0.f;
    }
    __shared__ float sg[KG_ * 3];
    if (k < KG_ * 3) sg[k] = gt[b * KG_ * 3 + k];
    __syncthreads();
    const float* p = xyz + (b * K_ + k) * 3;
    float x = p[0], y = p[1], z = p[2];
    float mn = 1e30f;
#pragma unroll 8
    for (int g = 0; g < KG_; g++) {
        float dx = x - sg[g * 3 + 0];
        float dy = y - sg[g * 3 + 1];
        float dz = z - sg[g * 3 + 2];
        mn = fminf(mn, dx * dx + dy * dy + dz * dz);
    }
    lbl[b * K_ + k] = (sqrtf(mn + 1e-6f) < 0.3f) ? 1.0f : 0.0f;

    int pv = pred[b * K_ + k];
    __shared__ int sc[K_];
    __shared__ int res[K_];
    sc[k] = pv;
    res[k] = k;
    __syncthreads();
    for (int off = 1; off < K_; off <<= 1) {
        int add = (k >= off) ? sc[k - off] : 0;
        __syncthreads();
        sc[k] += add;
        __syncthreads();
    }
    int num = sc[K_ - 1];
    int excl = sc[k] - pv;
    if (pv == 1) res[excl] = k;
    __syncthreads();
    idxo[b * K_ + k] = (float)((k < num) ? res[k] : k);
    if (k == 0) sum1[b] = (float)num;
}

// ===========================================================================
// wmma fp16 GEMM (fp32 accumulate): Y[b,m,n] = sum_c W[m,c]*X[b,c,n] + bias[m]
// grid = (2 n-halves, B_), 256 threads (8 warps), CTA tile 128x128,
// warp tile 32x64 (2x4 frags of 16x16x16), K chunked by 64, 2 CTA/SM.
// MODE 0: X = concat(X0,X1).  MODE 1: X = relu(X0*a[c]+d[c]).
// STATS : fused per-channel sum/sum^2 via shfl + atomics.
// ASM   : fuse 183-channel output assembly (bias+scale+xyz) into epilogue;
//         Y is then the final `out` pointer.
// Pads: ALDH=72 (144B row, conflict-free ldmatrix), BLDH=136 (272B row).
// Staging stores packed as uint4 (STS.128).
// ===========================================================================
#define ALDH 72
#define BLDH 136
#define DLD  68
// smem: Ash 128*72*2 = 18432 B, Bsh 64*136*2 = 17408 B -> 35840 B
//       Dsm reuse: 128*68*4 = 34816 B; ASM extras in [34816, 35840)
#define SMEM_BYTES 35840

template <int CIN, int MODE, int STATS, int ASM>
__global__ void __launch_bounds__(256, 2)
wmma_gemm(const float* __restrict__ W, const float* __restrict__ bias,
          const float* __restrict__ X0, const float* __restrict__ X1,
          const float* __restrict__ aa, const float* __restrict__ dd,
          float* __restrict__ Y, int M,
          float* __restrict__ sS, float* __restrict__ sS2,
          const float* __restrict__ xyz, const float* __restrict__ ms) {
    __shared__ __align__(16) char smbuf[SMEM_BYTES];
    __half* Ash = reinterpret_cast<__half*>(smbuf);                 // [128][ALDH]
    __half* Bsh = reinterpret_cast<__half*>(smbuf + 18432);         // [64][BLDH]
    float*  Dsm = reinterpret_cast<float*>(smbuf);                  // reused [128][DLD]

    int tid = threadIdx.x;
    int w = tid >> 5;
    int b = blockIdx.y;
    int n0 = blockIdx.x * 128;

    int mw = w >> 1;      // 0..3 -> m offset mw*32
    int nw = w & 1;       // 0..1 -> n offset nw*64

    wmma::fragment<wmma::accumulator, 16, 16, 16, float> acc[2][4];
#pragma unroll
    for (int i = 0; i < 2; i++)
#pragma unroll
        for (int j = 0; j < 4; j++)
            wmma::fill_fragment(acc[i][j], 0.f);

    // staging maps
    int arow = tid >> 1, ahalf = (tid & 1) * 32;   // A: 128 rows x 64 (2 thr/row)
    int brow = tid >> 2, bq = (tid & 3) * 32;      // B: 64 rows x 128 (4 thr/row)

    const float* xb0 = X0 + b * C_ * K_ + n0;
    const float* xb1 = (MODE == 0) ? X1 + b * C_ * K_ + n0 : nullptr;

    for (int c0 = 0; c0 < CIN; c0 += 64) {
        if (c0) __syncthreads();   // protect smem reuse after prior compute
        // ---- stage A: W[arow, c0+ahalf .. +32) -> regs (fp16) ----
        __align__(16) __half2 ha[16];
        if (arow < M) {
            const float* wp = W + arow * CIN + c0 + ahalf;
#pragma unroll
            for (int q = 0; q < 8; q++) {
                float4 v = *reinterpret_cast<const float4*>(wp + q * 4);
                ha[2 * q]     = __floats2half2_rn(v.x, v.y);
                ha[2 * q + 1] = __floats2half2_rn(v.z, v.w);
            }
        } else {
            __half2 z = __floats2half2_rn(0.f, 0.f);
#pragma unroll
            for (int q = 0; q < 16; q++) ha[q] = z;
        }
        // ---- stage B: X[c0+brow, n0+bq .. +32) -> regs (BN/relu + fp16) ----
        __align__(16) __half2 hb[16];
        {
            int cg = c0 + brow;
            const float* xp;
            if (MODE == 0)
                xp = (cg < C_) ? xb0 + cg * K_ : xb1 + (cg - C_) * K_;
            else
                xp = xb0 + cg * K_;
            float av = 0.f, dv = 0.f;
            if (MODE == 1) { av = __ldg(aa + cg); dv = __ldg(dd + cg); }
#pragma unroll
            for (int q = 0; q < 8; q++) {
                float4 v = *reinterpret_cast<const float4*>(xp + bq + q * 4);
                if (MODE == 1) {
                    v.x = fmaxf(fmaf(v.x, av, dv), 0.f);
                    v.y = fmaxf(fmaf(v.y, av, dv), 0.f);
                    v.z = fmaxf(fmaf(v.z, av, dv), 0.f);
                    v.w = fmaxf(fmaf(v.w, av, dv), 0.f);
                }
                hb[2 * q]     = __floats2half2_rn(v.x, v.y);
                hb[2 * q + 1] = __floats2half2_rn(v.z, v.w);
            }
        }
        // ---- packed STS.128 stores ----
        {
            uint4* da = reinterpret_cast<uint4*>(Ash + arow * ALDH + ahalf);
            const uint4* sa = reinterpret_cast<const uint4*>(ha);
#pragma unroll
            for (int r = 0; r < 4; r++) da[r] = sa[r];
            uint4* db = reinterpret_cast<uint4*>(Bsh + brow * BLDH + bq);
            const uint4* sb = reinterpret_cast<const uint4*>(hb);
#pragma unroll
            for (int r = 0; r < 4; r++) db[r] = sb[r];
        }
        __syncthreads();

#pragma unroll
        for (int ks = 0; ks < 4; ks++) {
            wmma::fragment<wmma::matrix_a, 16, 16, 16, __half,
                           wmma::row_major> af[2];
            wmma::fragment<wmma::matrix_b, 16, 16, 16, __half,
                           wmma::row_major> bf[4];
#pragma unroll
            for (int i = 0; i < 2; i++)
                wmma::load_matrix_sync(af[i],
                    Ash + (mw * 32 + i * 16) * ALDH + ks * 16, ALDH);
#pragma unroll
            for (int j = 0; j < 4; j++)
                wmma::load_matrix_sync(bf[j],
                    Bsh + ks * 16 * BLDH + nw * 64 + j * 16, BLDH);
#pragma unroll
            for (int i = 0; i < 2; i++)
#pragma unroll
                for (int j = 0; j < 4; j++)
                    wmma::mma_sync(acc[i][j], af[i], bf[j], acc[i][j]);
        }
    }
    __syncthreads();

    // ---- epilogue: two n-waves through smem ----
    float* sms   = Dsm + C_ * DLD;    // [54]  (bytes 34816..)
    float* sbias = sms + 54;          // [117]
    if (ASM) {
        if (tid < 54)   sms[tid]   = __ldg(ms + tid);
        if (tid < OUTC) sbias[tid] = __ldg(bias + tid);
    }

    int erow = tid >> 1;                 // 0..127
    int eoff = (tid & 1) * 32;
    float bb = (!ASM && erow < M) ? __ldg(bias + erow) : 0.f;
    float s = 0.f, s2 = 0.f;

#pragma unroll
    for (int wave = 0; wave < 2; wave++) {
        if (nw == wave) {
#pragma unroll
            for (int i = 0; i < 2; i++)
#pragma unroll
                for (int j = 0; j < 4; j++)
                    wmma::store_matrix_sync(
                        Dsm + (mw * 32 + i * 16) * DLD + j * 16,
                        acc[i][j], DLD, wmma::mem_row_major);
        }
        __syncthreads();
        if (!ASM) {
            if (erow < M) {
                float* yp = Y + b * M * K_ + erow * K_ + n0 + wave * 64 + eoff;
                const float* sp = Dsm + erow * DLD + eoff;
#pragma unroll
                for (int q = 0; q < 8; q++) {
                    float4 v = *reinterpret_cast<const float4*>(sp + q * 4);
                    v.x += bb; v.y += bb; v.z += bb; v.w += bb;
                    *reinterpret_cast<float4*>(yp + q * 4) = v;
                    if (STATS) {
                        s += v.x + v.y + v.z + v.w;
                        s2 = fmaf(v.x, v.x, s2); s2 = fmaf(v.y, v.y, s2);
                        s2 = fmaf(v.z, v.z, s2); s2 = fmaf(v.w, v.w, s2);
                    }
                }
            }
        } else {
            // fused 183-channel output assembly; Y == out base pointer
            int kbase = n0 + wave * 64;
            float* op = Y + ((size_t)b * K_ + kbase) * OCH;
            for (int e = tid; e < 64 * OCH; e += 256) {
                int kk = e / OCH;
                int ch = e - kk * OCH;
                int o;
                float scale = 1.f, add = 0.f;
                if (ch < 27) {               // center(+xyz), hs, hrn
                    o = ch;
                    if (ch < 3) add = xyz[((size_t)b * K_ + kbase + kk) * 3 + ch];
                } else if (ch < 39) {        // hr = hrn * pi/12
                    o = ch - 12;
                    scale = 0.26179938779914943f;
                } else if (ch < 111) {       // ss, srn
                    o = ch - 12;
                } else if (ch < 165) {       // sr = srn * mean_size
                    o = ch - 66;
                    scale = sms[ch - 111];
                } else {                     // sem
                    o = ch - 66;
                }
                op[e] = (Dsm[o * DLD + kk] + sbias[o]) * scale + add;
            }
        }
        __syncthreads();
    }

    if (STATS && erow < M) {
        s  += __shfl_xor_sync(0xffffffffu, s, 1);
        s2 += __shfl_xor_sync(0xffffffffu, s2, 1);
        if ((tid & 1) == 0) {
            atomicAdd(&sS[erow], s);
            atomicAdd(&sS2[erow], s2);
        }
    }
}

// ===========================================================================
// finalize BN fold: relu_bn(x) = relu(x*a + d)
// ===========================================================================
__global__ void finalize_kernel(const float* __restrict__ g,
                                const float* __restrict__ be,
                                const float* __restrict__ sS,
                                const float* __restrict__ sS2,
                                float* __restrict__ a, float* __restrict__ d) {
    int c = threadIdx.x;
    if (c < C_) {
        const float invN = 1.0f / (B_ * K_);
        float mean = sS[c] * invN;
        float var = sS2[c] * invN - mean * mean;
        float rstd = rsqrtf(var + 1e-5f);
        float av = rstd * g[c];
        a[c] = av;
        d[c] = be[c] - mean * av;
    }
}

// ===========================================================================
extern "C" void kernel_launch(void* const* d_in, const int* in_sizes, int n_in,
                              void* d_out, int out_size) {
    (void)in_sizes; (void)n_in; (void)out_size;
    const float* xyz      = (const float*)d_in[0];
    const float* features = (const float*)d_in[1];
    const float* rn       = (const float*)d_in[2];
    const float* gt       = (const float*)d_in[3];
    const int*   pred     = (const int*)d_in[4];   // int32
    const float* W1 = (const float*)d_in[5];
    const float* b1 = (const float*)d_in[6];
    const float* g1 = (const float*)d_in[7];
    const float* be1 = (const float*)d_in[8];
    const float* W2 = (const float*)d_in[9];
    const float* b2 = (const float*)d_in[10];
    const float* g2 = (const float*)d_in[11];
    const float* be2 = (const float*)d_in[12];
    const float* W3 = (const float*)d_in[13];
    const float* b3 = (const float*)d_in[14];
    const float* ms = (const float*)d_in[15];
    float* out = (float*)d_out;

    const int OFF_IDX = B_ * K_ * OCH;
    const int OFF_SUM = OFF_IDX + B_ * K_;
    const int OFF_LBL = OFF_SUM + B_;

    float *p_net1, *p_net2, *p_s, *p_s2, *p_a, *p_d;
    cudaGetSymbolAddress((void**)&p_net1, g_net1);
    cudaGetSymbolAddress((void**)&p_net2, g_net2);
    cudaGetSymbolAddress((void**)&p_s,    g_s);
    cudaGetSymbolAddress((void**)&p_s2,   g_s2);
    cudaGetSymbolAddress((void**)&p_a,    g_a);
    cudaGetSymbolAddress((void**)&p_d,    g_d);

    prep_kernel<<<B_, K_>>>(xyz, gt, pred,
                            out + OFF_LBL, out + OFF_IDX, out + OFF_SUM);

    dim3 gg(2, B_);
    wmma_gemm<256, 0, 1, 0><<<gg, 256>>>(W1, b1, features, rn, nullptr, nullptr,
                                         p_net1, C_, p_s, p_s2,
                                         nullptr, nullptr);
    finalize_kernel<<<1, 128>>>(g1, be1, p_s, p_s2, p_a, p_d);
    wmma_gemm<128, 1, 1, 0><<<gg, 256>>>(W2, b2, p_net1, nullptr, p_a, p_d,
                                         p_net2, C_, p_s + C_, p_s2 + C_,
                                         nullptr, nullptr);
    finalize_kernel<<<1, 128>>>(g2, be2, p_s + C_, p_s2 + C_, p_a + C_, p_d + C_);
    // layer 3 + fused output assembly (writes `out` directly)
    wmma_gemm<128, 1, 0, 1><<<gg, 256>>>(W3, b3, p_net2, nullptr,
                                         p_a + C_, p_d + C_,
                                         out, OUTC, nullptr, nullptr,
                                         xyz, ms);
}

// round 12
// speedup vs baseline: 2.3700x; 1.0255x over previous
#include <cuda_runtime.h>
#include <cuda_fp16.h>
#include <mma.h>
#include <cstdint>

using namespace nvcuda;

#define B_   256
#define K_   256
#define C_   128
#define KG_  64
#define OUTC 117
#define OCH  183

// scratch (allocation-free rule: __device__ globals)
__device__ float g_net1[B_ * C_ * K_];   // layer1 output, no bias (B,128,256)
__device__ float g_net2[B_ * C_ * K_];   // layer2 output, no bias
__device__ float g_s[2][C_];             // BN sum accumulators
__device__ float g_s2[2][C_];            // BN sum-of-squares accumulators
__device__ float g_a[2][C_], g_d[2][C_]; // folded BN scale/shift
__device__ __half g_W1h[C_ * 2 * C_];    // fp16 W1 [128][256]
__device__ __half g_W2h[C_ * C_];        // fp16 W2 [128][128]
__device__ __half g_W3h[C_ * C_];        // fp16 W3 [128][128] (rows 117.. zero)

// ===========================================================================
// convw: one-time fp16 conversion of the three weight matrices
// 65536 elements total; grid 64 x 256, 4 elems/thread
// ===========================================================================
__global__ void convw_kernel(const float* __restrict__ W1,
                             const float* __restrict__ W2,
                             const float* __restrict__ W3) {
    int t = (blockIdx.x * 256 + threadIdx.x) * 4;
#pragma unroll
    for (int q = 0; q < 4; q++) {
        int i = t + q;
        if (i < 32768) {
            g_W1h[i] = __float2half_rn(W1[i]);
        } else if (i < 49152) {
            g_W2h[i - 32768] = __float2half_rn(W2[i - 32768]);
        } else {
            int j = i - 49152;
            int row = j >> 7;
            g_W3h[j] = (row < OUTC) ? __float2half_rn(W3[row * C_ + (j & 127)])
                                    : __float2half_rn(0.f);
        }
    }
}

// ===========================================================================
// prep: objectness_label + get_index + zero BN accumulators (fused)
// ===========================================================================
__global__ void prep_kernel(const float* __restrict__ xyz,
                            const float* __restrict__ gt,
                            const int* __restrict__ pred,
                            float* __restrict__ lbl,
                            float* __restrict__ idxo,
                            float* __restrict__ sum1) {
    int b = blockIdx.x, k = threadIdx.x;
    if (b == 0 && k < C_) {
        g_s[0][k] = 0.f; g_s[1][k] = 0.f;
        g_s2[0][k] = 0.f; g_s2[1][k] = 0.f;
    }
    __shared__ float sg[KG_ * 3];
    if (k < KG_ * 3) sg[k] = gt[b * KG_ * 3 + k];
    __syncthreads();
    const float* p = xyz + (b * K_ + k) * 3;
    float x = p[0], y = p[1], z = p[2];
    float mn = 1e30f;
#pragma unroll 8
    for (int g = 0; g < KG_; g++) {
        float dx = x - sg[g * 3 + 0];
        float dy = y - sg[g * 3 + 1];
        float dz = z - sg[g * 3 + 2];
        mn = fminf(mn, dx * dx + dy * dy + dz * dz);
    }
    lbl[b * K_ + k] = (sqrtf(mn + 1e-6f) < 0.3f) ? 1.0f : 0.0f;

    int pv = pred[b * K_ + k];
    __shared__ int sc[K_];
    __shared__ int res[K_];
    sc[k] = pv;
    res[k] = k;
    __syncthreads();
    for (int off = 1; off < K_; off <<= 1) {
        int add = (k >= off) ? sc[k - off] : 0;
        __syncthreads();
        sc[k] += add;
        __syncthreads();
    }
    int num = sc[K_ - 1];
    int excl = sc[k] - pv;
    if (pv == 1) res[excl] = k;
    __syncthreads();
    idxo[b * K_ + k] = (float)((k < num) ? res[k] : k);
    if (k == 0) sum1[b] = (float)num;
}

// ===========================================================================
// wmma fp16 GEMM (fp32 accum): Y[b,m,n] = sum_c W[m,c]*X[b,c,n]  (no bias;
// BN cancels constant channel shifts, so b1/b2 are dropped exactly).
// A-fragments load DIRECTLY from global fp16 W (L1-resident, shared by all
// CTAs) — no A smem staging. B staged via smem with fused BN/relu + fp16.
// grid = (2 n-halves, B_), 256 threads (8 warps), CTA tile 128x128,
// warp tile 32x64, K chunked by 64, 2 CTA/SM.
// MODE 0: X = concat(X0,X1).  MODE 1: X = relu(X0*a[c]+d[c]).
// STATS : fused per-channel sum/sum^2 via shfl + atomics.
// ASM   : fuse 183-channel output assembly (uses bias b3 + scale + xyz).
// ===========================================================================
#define BLDH 136   // Bs leading dim in halves (272B rows; conflict-free LDSM)
#define DLD  68
// smem: Bsh 64*136*2 = 17408 B; Dsm reuse 128*68*4 = 34816 B; extras 684 B
#define SMEM_BYTES 35840

template <int CIN, int MODE, int STATS, int ASM>
__global__ void __launch_bounds__(256, 2)
wmma_gemm(const __half* __restrict__ gW, const float* __restrict__ bias,
          const float* __restrict__ X0, const float* __restrict__ X1,
          const float* __restrict__ aa, const float* __restrict__ dd,
          float* __restrict__ Y,
          float* __restrict__ sS, float* __restrict__ sS2,
          const float* __restrict__ xyz, const float* __restrict__ ms) {
    __shared__ __align__(16) char smbuf[SMEM_BYTES];
    __half* Bsh = reinterpret_cast<__half*>(smbuf);        // [64][BLDH]
    float*  Dsm = reinterpret_cast<float*>(smbuf);         // reused [128][DLD]

    int tid = threadIdx.x;
    int w = tid >> 5;
    int b = blockIdx.y;
    int n0 = blockIdx.x * 128;

    int mw = w >> 1;      // 0..3 -> m offset mw*32
    int nw = w & 1;       // 0..1 -> n offset nw*64

    wmma::fragment<wmma::accumulator, 16, 16, 16, float> acc[2][4];
#pragma unroll
    for (int i = 0; i < 2; i++)
#pragma unroll
        for (int j = 0; j < 4; j++)
            wmma::fill_fragment(acc[i][j], 0.f);

    // B staging map: 64 rows x 128 cols, 4 thr/row
    int brow = tid >> 2, bq = (tid & 3) * 32;

    const float* xb0 = X0 + b * C_ * K_ + n0;
    const float* xb1 = (MODE == 0) ? X1 + b * C_ * K_ + n0 : nullptr;

    for (int c0 = 0; c0 < CIN; c0 += 64) {
        if (c0) __syncthreads();   // protect smem reuse after prior compute
        // ---- stage B: X[c0+brow, n0+bq .. +32) -> regs (BN/relu + fp16) ----
        __align__(16) __half2 hb[16];
        {
            int cg = c0 + brow;
            const float* xp;
            if (MODE == 0)
                xp = (cg < C_) ? xb0 + cg * K_ : xb1 + (cg - C_) * K_;
            else
                xp = xb0 + cg * K_;
            float av = 0.f, dv = 0.f;
            if (MODE == 1) { av = __ldg(aa + cg); dv = __ldg(dd + cg); }
#pragma unroll
            for (int q = 0; q < 8; q++) {
                float4 v = *reinterpret_cast<const float4*>(xp + bq + q * 4);
                if (MODE == 1) {
                    v.x = fmaxf(fmaf(v.x, av, dv), 0.f);
                    v.y = fmaxf(fmaf(v.y, av, dv), 0.f);
                    v.z = fmaxf(fmaf(v.z, av, dv), 0.f);
                    v.w = fmaxf(fmaf(v.w, av, dv), 0.f);
                }
                hb[2 * q]     = __floats2half2_rn(v.x, v.y);
                hb[2 * q + 1] = __floats2half2_rn(v.z, v.w);
            }
            uint4* db = reinterpret_cast<uint4*>(Bsh + brow * BLDH + bq);
            const uint4* sb = reinterpret_cast<const uint4*>(hb);
#pragma unroll
            for (int r = 0; r < 4; r++) db[r] = sb[r];
        }
        __syncthreads();

#pragma unroll
        for (int ks = 0; ks < 4; ks++) {
            wmma::fragment<wmma::matrix_a, 16, 16, 16, __half,
                           wmma::row_major> af[2];
            wmma::fragment<wmma::matrix_b, 16, 16, 16, __half,
                           wmma::row_major> bf[4];
            // A fragments straight from global fp16 W (L1 hits)
#pragma unroll
            for (int i = 0; i < 2; i++)
                wmma::load_matrix_sync(af[i],
                    gW + (mw * 32 + i * 16) * CIN + c0 + ks * 16, CIN);
#pragma unroll
            for (int j = 0; j < 4; j++)
                wmma::load_matrix_sync(bf[j],
                    Bsh + ks * 16 * BLDH + nw * 64 + j * 16, BLDH);
#pragma unroll
            for (int i = 0; i < 2; i++)
#pragma unroll
                for (int j = 0; j < 4; j++)
                    wmma::mma_sync(acc[i][j], af[i], bf[j], acc[i][j]);
        }
    }
    __syncthreads();

    // ---- epilogue: two n-waves through smem ----
    float* sms   = Dsm + C_ * DLD;    // [54]
    float* sbias = sms + 54;          // [117]
    if (ASM) {
        if (tid < 54)   sms[tid]   = __ldg(ms + tid);
        if (tid < OUTC) sbias[tid] = __ldg(bias + tid);
    }

    int erow = tid >> 1;                 // 0..127
    int eoff = (tid & 1) * 32;
    float s = 0.f, s2 = 0.f;

#pragma unroll
    for (int wave = 0; wave < 2; wave++) {
        if (nw == wave) {
#pragma unroll
            for (int i = 0; i < 2; i++)
#pragma unroll
                for (int j = 0; j < 4; j++)
                    wmma::store_matrix_sync(
                        Dsm + (mw * 32 + i * 16) * DLD + j * 16,
                        acc[i][j], DLD, wmma::mem_row_major);
        }
        __syncthreads();
        if (!ASM) {
            float* yp = Y + b * C_ * K_ + erow * K_ + n0 + wave * 64 + eoff;
            const float* sp = Dsm + erow * DLD + eoff;
#pragma unroll
            for (int q = 0; q < 8; q++) {
                float4 v = *reinterpret_cast<const float4*>(sp + q * 4);
                *reinterpret_cast<float4*>(yp + q * 4) = v;
                if (STATS) {
                    s += v.x + v.y + v.z + v.w;
                    s2 = fmaf(v.x, v.x, s2); s2 = fmaf(v.y, v.y, s2);
                    s2 = fmaf(v.z, v.z, s2); s2 = fmaf(v.w, v.w, s2);
                }
            }
        } else {
            // fused 183-channel output assembly; Y == out base pointer
            int kbase = n0 + wave * 64;
            float* op = Y + ((size_t)b * K_ + kbase) * OCH;
            for (int e = tid; e < 64 * OCH; e += 256) {
                int kk = e / OCH;
                int ch = e - kk * OCH;
                int o;
                float scale = 1.f, add = 0.f;
                if (ch < 27) {               // center(+xyz), hs, hrn
                    o = ch;
                    if (ch < 3) add = xyz[((size_t)b * K_ + kbase + kk) * 3 + ch];
                } else if (ch < 39) {        // hr = hrn * pi/12
                    o = ch - 12;
                    scale = 0.26179938779914943f;
                } else if (ch < 111) {       // ss, srn
                    o = ch - 12;
                } else if (ch < 165) {       // sr = srn * mean_size
                    o = ch - 66;
                    scale = sms[ch - 111];
                } else {                     // sem
                    o = ch - 66;
                }
                op[e] = (Dsm[o * DLD + kk] + sbias[o]) * scale + add;
            }
        }
        __syncthreads();
    }

    if (STATS) {
        s  += __shfl_xor_sync(0xffffffffu, s, 1);
        s2 += __shfl_xor_sync(0xffffffffu, s2, 1);
        if ((tid & 1) == 0) {
            atomicAdd(&sS[erow], s);
            atomicAdd(&sS2[erow], s2);
        }
    }
}

// ===========================================================================
// finalize BN fold: relu_bn(x) = relu(x*a + d)  (stats are bias-free; exact)
// ===========================================================================
__global__ void finalize_kernel(const float* __restrict__ g,
                                const float* __restrict__ be,
                                const float* __restrict__ sS,
                                const float* __restrict__ sS2,
                                float* __restrict__ a, float* __restrict__ d) {
    int c = threadIdx.x;
    if (c < C_) {
        const float invN = 1.0f / (B_ * K_);
        float mean = sS[c] * invN;
        float var = sS2[c] * invN - mean * mean;
        float rstd = rsqrtf(var + 1e-5f);
        float av = rstd * g[c];
        a[c] = av;
        d[c] = be[c] - mean * av;
    }
}

// ===========================================================================
extern "C" void kernel_launch(void* const* d_in, const int* in_sizes, int n_in,
                              void* d_out, int out_size) {
    (void)in_sizes; (void)n_in; (void)out_size;
    const float* xyz      = (const float*)d_in[0];
    const float* features = (const float*)d_in[1];
    const float* rn       = (const float*)d_in[2];
    const float* gt       = (const float*)d_in[3];
    const int*   pred     = (const int*)d_in[4];   // int32
    const float* W1 = (const float*)d_in[5];
    const float* g1 = (const float*)d_in[7];
    const float* be1 = (const float*)d_in[8];
    const float* W2 = (const float*)d_in[9];
    const float* g2 = (const float*)d_in[11];
    const float* be2 = (const float*)d_in[12];
    const float* W3 = (const float*)d_in[13];
    const float* b3 = (const float*)d_in[14];
    const float* ms = (const float*)d_in[15];
    float* out = (float*)d_out;

    const int OFF_IDX = B_ * K_ * OCH;
    const int OFF_SUM = OFF_IDX + B_ * K_;
    const int OFF_LBL = OFF_SUM + B_;

    float *p_net1, *p_net2, *p_s, *p_s2, *p_a, *p_d;
    __half *p_W1h, *p_W2h, *p_W3h;
    cudaGetSymbolAddress((void**)&p_net1, g_net1);
    cudaGetSymbolAddress((void**)&p_net2, g_net2);
    cudaGetSymbolAddress((void**)&p_s,    g_s);
    cudaGetSymbolAddress((void**)&p_s2,   g_s2);
    cudaGetSymbolAddress((void**)&p_a,    g_a);
    cudaGetSymbolAddress((void**)&p_d,    g_d);
    cudaGetSymbolAddress((void**)&p_W1h,  g_W1h);
    cudaGetSymbolAddress((void**)&p_W2h,  g_W2h);
    cudaGetSymbolAddress((void**)&p_W3h,  g_W3h);

    convw_kernel<<<64, 256>>>(W1, W2, W3);
    prep_kernel<<<B_, K_>>>(xyz, gt, pred,
                            out + OFF_LBL, out + OFF_IDX, out + OFF_SUM);

    dim3 gg(2, B_);
    wmma_gemm<256, 0, 1, 0><<<gg, 256>>>(p_W1h, nullptr, features, rn,
                                         nullptr, nullptr,
                                         p_net1, p_s, p_s2, nullptr, nullptr);
    finalize_kernel<<<1, 128>>>(g1, be1, p_s, p_s2, p_a, p_d);
    wmma_gemm<128, 1, 1, 0><<<gg, 256>>>(p_W2h, nullptr, p_net1, nullptr,
                                         p_a, p_d,
                                         p_net2, p_s + C_, p_s2 + C_,
                                         nullptr, nullptr);
    finalize_kernel<<<1, 128>>>(g2, be2, p_s + C_, p_s2 + C_, p_a + C_, p_d + C_);
    // layer 3 + fused output assembly (writes `out` directly; b3 applied here)
    wmma_gemm<128, 1, 0, 1><<<gg, 256>>>(p_W3h, b3, p_net2, nullptr,
                                         p_a + C_, p_d + C_,
                                         out, nullptr, nullptr,
                                         xyz, ms);
}

// round 13
// speedup vs baseline: 2.4443x; 1.0313x over previous
#include <cuda_runtime.h>
#include <cuda_fp16.h>
#include <mma.h>
#include <cstdint>

using namespace nvcuda;

#define B_   256
#define K_   256
#define C_   128
#define KG_  64
#define OUTC 117
#define OCH  183

// scratch (allocation-free rule: __device__ globals)
__device__ float g_net1[B_ * C_ * K_];   // layer1 output, no bias (B,128,256)
__device__ float g_net2[B_ * C_ * K_];   // layer2 output, no bias
__device__ float g_s[2][C_];             // BN sum accumulators
__device__ float g_s2[2][C_];            // BN sum-of-squares accumulators
__device__ __half g_W1h[C_ * 2 * C_];    // fp16 W1 [128][256]
__device__ __half g_W2h[C_ * C_];        // fp16 W2 [128][128]
__device__ __half g_W3h[C_ * C_];        // fp16 W3 [128][128] (rows 117.. zero)

// ===========================================================================
// prep: weight fp16 conversion + objectness_label + get_index + zero stats
// grid = B_ (256 blocks), block = 256 threads; block b converts weight
// elements [b*256, b*256+256).
// ===========================================================================
__global__ void prep_kernel(const float* __restrict__ xyz,
                            const float* __restrict__ gt,
                            const int* __restrict__ pred,
                            const float* __restrict__ W1,
                            const float* __restrict__ W2,
                            const float* __restrict__ W3,
                            float* __restrict__ lbl,
                            float* __restrict__ idxo,
                            float* __restrict__ sum1) {
    int b = blockIdx.x, k = threadIdx.x;

    // ---- weight conversion: 1 element per thread ----
    {
        int i = b * 256 + k;
        if (i < 32768) {
            g_W1h[i] = __float2half_rn(W1[i]);
        } else if (i < 49152) {
            g_W2h[i - 32768] = __float2half_rn(W2[i - 32768]);
        } else {
            int j = i - 49152;
            int row = j >> 7;
            g_W3h[j] = (row < OUTC) ? __float2half_rn(W3[row * C_ + (j & 127)])
                                    : __float2half_rn(0.f);
        }
    }
    if (b == 0 && k < C_) {
        g_s[0][k] = 0.f; g_s[1][k] = 0.f;
        g_s2[0][k] = 0.f; g_s2[1][k] = 0.f;
    }

    // ---- label ----
    __shared__ float sg[KG_ * 3];
    if (k < KG_ * 3) sg[k] = gt[b * KG_ * 3 + k];
    __syncthreads();
    const float* p = xyz + (b * K_ + k) * 3;
    float x = p[0], y = p[1], z = p[2];
    float mn = 1e30f;
#pragma unroll 8
    for (int g = 0; g < KG_; g++) {
        float dx = x - sg[g * 3 + 0];
        float dy = y - sg[g * 3 + 1];
        float dz = z - sg[g * 3 + 2];
        mn = fminf(mn, dx * dx + dy * dy + dz * dz);
    }
    lbl[b * K_ + k] = (sqrtf(mn + 1e-6f) < 0.3f) ? 1.0f : 0.0f;

    // ---- index (pred is int32: JAX x64 disabled) ----
    int pv = pred[b * K_ + k];
    __shared__ int sc[K_];
    __shared__ int res[K_];
    sc[k] = pv;
    res[k] = k;
    __syncthreads();
    for (int off = 1; off < K_; off <<= 1) {
        int add = (k >= off) ? sc[k - off] : 0;
        __syncthreads();
        sc[k] += add;
        __syncthreads();
    }
    int num = sc[K_ - 1];
    int excl = sc[k] - pv;
    if (pv == 1) res[excl] = k;
    __syncthreads();
    idxo[b * K_ + k] = (float)((k < num) ? res[k] : k);
    if (k == 0) sum1[b] = (float)num;
}

// ===========================================================================
// wmma fp16 GEMM (fp32 accum): Y[b,m,n] = sum_c W[m,c]*X[b,c,n]
// (no bias in GEMM1/2 — BN cancels channel shifts exactly; b3 applied in ASM)
// FULL-K staging: Bsh holds a 128x128 B tile (one chunk); CIN=256 runs two
// chunks (chunk0 = X0/features, chunk1 = X1/rn). One sync pair per chunk;
// mma phase is 8 uninterrupted k-steps. A frags from global fp16 W (L1).
// FIN  : compute folded BN (a,d) per-CTA from g_s/g_s2 at kernel start.
// STATS: fused per-channel sum/sum^2 via shfl + atomics.
// ASM  : fuse 183-channel output assembly (bias b3 + scale + xyz).
// grid = (2 n-halves, B_), 256 threads (8 warps), warp tile 32x64, 2 CTA/SM.
// ===========================================================================
#define BLDH 136   // Bs leading dim in halves (272B rows; conflict-light)
#define DLD  68
// smem: Bsh 128*136*2 = 34816 B (aliased by Dsm 128*68*4 = 34816 B)
//       sA 512 B | sD 512 B | sms 216+ | sbias 468 -> total 36544
#define SMEM_BYTES 36544

template <int CIN, int FIN, int STATS, int ASM>
__global__ void __launch_bounds__(256, 2)
wmma_gemm(const __half* __restrict__ gW, const float* __restrict__ bias,
          const float* __restrict__ X0, const float* __restrict__ X1,
          const float* __restrict__ gam, const float* __restrict__ bet,
          const float* __restrict__ inS, const float* __restrict__ inS2,
          float* __restrict__ Y,
          float* __restrict__ sS, float* __restrict__ sS2,
          const float* __restrict__ xyz, const float* __restrict__ ms) {
    __shared__ __align__(16) char smbuf[SMEM_BYTES];
    __half* Bsh = reinterpret_cast<__half*>(smbuf);        // [128][BLDH]
    float*  Dsm = reinterpret_cast<float*>(smbuf);         // reused [128][DLD]
    float*  sA    = reinterpret_cast<float*>(smbuf + 34816);  // [128]
    float*  sD    = reinterpret_cast<float*>(smbuf + 35328);  // [128]
    float*  sms   = reinterpret_cast<float*>(smbuf + 35840);  // [54]
    float*  sbias = reinterpret_cast<float*>(smbuf + 36056);  // [117]

    int tid = threadIdx.x;
    int w = tid >> 5;
    int b = blockIdx.y;
    int n0 = blockIdx.x * 128;

    int mw = w >> 1;      // 0..3 -> m offset mw*32
    int nw = w & 1;       // 0..1 -> n offset nw*64

    // ---- in-kernel BN finalize: (a,d) from producer stats ----
    if (FIN) {
        if (tid < C_) {
            const float invN = 1.0f / (B_ * K_);
            float mean = inS[tid] * invN;
            float var = inS2[tid] * invN - mean * mean;
            float rstd = rsqrtf(var + 1e-5f);
            float av = rstd * __ldg(gam + tid);
            sA[tid] = av;
            sD[tid] = __ldg(bet + tid) - mean * av;
        }
        __syncthreads();
    }

    wmma::fragment<wmma::accumulator, 16, 16, 16, float> acc[2][4];
#pragma unroll
    for (int i = 0; i < 2; i++)
#pragma unroll
        for (int j = 0; j < 4; j++)
            wmma::fill_fragment(acc[i][j], 0.f);

    // B staging map: 128 rows, 2 threads/row, 64 floats each
    int brow = tid >> 1;
    int bhalf = (tid & 1) * 64;

    const int NCHUNK = CIN / 128;
#pragma unroll
    for (int cc = 0; cc < NCHUNK; cc++) {
        if (cc) __syncthreads();
        // ---- stage B chunk: X[cc*128+brow, n0+bhalf .. +64) ----
        {
            const float* base = (NCHUNK == 2)
                ? ((cc == 0) ? X0 : X1)   // concat along c
                : X0;
            const float* xp = base + b * C_ * K_ + brow * K_ + n0 + bhalf;
            __half* dst = Bsh + brow * BLDH + bhalf;
            float av = 0.f, dv = 0.f;
            if (FIN) { av = sA[brow]; dv = sD[brow]; }
#pragma unroll
            for (int g = 0; g < 2; g++) {          // 2 groups of 32 floats
                float4 v[8];
#pragma unroll
                for (int q = 0; q < 8; q++)
                    v[q] = *reinterpret_cast<const float4*>(xp + g * 32 + q * 4);
                __align__(16) __half2 h[16];
#pragma unroll
                for (int q = 0; q < 8; q++) {
                    if (FIN) {
                        v[q].x = fmaxf(fmaf(v[q].x, av, dv), 0.f);
                        v[q].y = fmaxf(fmaf(v[q].y, av, dv), 0.f);
                        v[q].z = fmaxf(fmaf(v[q].z, av, dv), 0.f);
                        v[q].w = fmaxf(fmaf(v[q].w, av, dv), 0.f);
                    }
                    h[2 * q]     = __floats2half2_rn(v[q].x, v[q].y);
                    h[2 * q + 1] = __floats2half2_rn(v[q].z, v[q].w);
                }
                uint4* db = reinterpret_cast<uint4*>(dst + g * 32);
                const uint4* sb = reinterpret_cast<const uint4*>(h);
#pragma unroll
                for (int r = 0; r < 4; r++) db[r] = sb[r];
            }
        }
        __syncthreads();

        // ---- one long mma phase: 8 k-steps ----
#pragma unroll
        for (int ks = 0; ks < 8; ks++) {
            wmma::fragment<wmma::matrix_a, 16, 16, 16, __half,
                           wmma::row_major> af[2];
            wmma::fragment<wmma::matrix_b, 16, 16, 16, __half,
                           wmma::row_major> bf[4];
#pragma unroll
            for (int i = 0; i < 2; i++)
                wmma::load_matrix_sync(af[i],
                    gW + (mw * 32 + i * 16) * CIN + cc * 128 + ks * 16, CIN);
#pragma unroll
            for (int j = 0; j < 4; j++)
                wmma::load_matrix_sync(bf[j],
                    Bsh + ks * 16 * BLDH + nw * 64 + j * 16, BLDH);
#pragma unroll
            for (int i = 0; i < 2; i++)
#pragma unroll
                for (int j = 0; j < 4; j++)
                    wmma::mma_sync(acc[i][j], af[i], bf[j], acc[i][j]);
        }
    }
    __syncthreads();

    // ---- epilogue: two n-waves through smem ----
    if (ASM) {
        if (tid < 54)   sms[tid]   = __ldg(ms + tid);
        if (tid < OUTC) sbias[tid] = __ldg(bias + tid);
    }

    int erow = tid >> 1;                 // 0..127
    int eoff = (tid & 1) * 32;
    float s = 0.f, s2 = 0.f;

#pragma unroll
    for (int wave = 0; wave < 2; wave++) {
        if (nw == wave) {
#pragma unroll
            for (int i = 0; i < 2; i++)
#pragma unroll
                for (int j = 0; j < 4; j++)
                    wmma::store_matrix_sync(
                        Dsm + (mw * 32 + i * 16) * DLD + j * 16,
                        acc[i][j], DLD, wmma::mem_row_major);
        }
        __syncthreads();
        if (!ASM) {
            float* yp = Y + b * C_ * K_ + erow * K_ + n0 + wave * 64 + eoff;
            const float* sp = Dsm + erow * DLD + eoff;
#pragma unroll
            for (int q = 0; q < 8; q++) {
                float4 v = *reinterpret_cast<const float4*>(sp + q * 4);
                *reinterpret_cast<float4*>(yp + q * 4) = v;
                if (STATS) {
                    s += v.x + v.y + v.z + v.w;
                    s2 = fmaf(v.x, v.x, s2); s2 = fmaf(v.y, v.y, s2);
                    s2 = fmaf(v.z, v.z, s2); s2 = fmaf(v.w, v.w, s2);
                }
            }
        } else {
            // fused 183-channel output assembly; Y == out base pointer
            int kbase = n0 + wave * 64;
            float* op = Y + ((size_t)b * K_ + kbase) * OCH;
            for (int e = tid; e < 64 * OCH; e += 256) {
                int kk = e / OCH;
                int ch = e - kk * OCH;
                int o;
                float scale = 1.f, add = 0.f;
                if (ch < 27) {               // center(+xyz), hs, hrn
                    o = ch;
                    if (ch < 3) add = xyz[((size_t)b * K_ + kbase + kk) * 3 + ch];
                } else if (ch < 39) {        // hr = hrn * pi/12
                    o = ch - 12;
                    scale = 0.26179938779914943f;
                } else if (ch < 111) {       // ss, srn
                    o = ch - 12;
                } else if (ch < 165) {       // sr = srn * mean_size
                    o = ch - 66;
                    scale = sms[ch - 111];
                } else {                     // sem
                    o = ch - 66;
                }
                op[e] = (Dsm[o * DLD + kk] + sbias[o]) * scale + add;
            }
        }
        __syncthreads();
    }

    if (STATS) {
        s  += __shfl_xor_sync(0xffffffffu, s, 1);
        s2 += __shfl_xor_sync(0xffffffffu, s2, 1);
        if ((tid & 1) == 0) {
            atomicAdd(&sS[erow], s);
            atomicAdd(&sS2[erow], s2);
        }
    }
}

// ===========================================================================
extern "C" void kernel_launch(void* const* d_in, const int* in_sizes, int n_in,
                              void* d_out, int out_size) {
    (void)in_sizes; (void)n_in; (void)out_size;
    const float* xyz      = (const float*)d_in[0];
    const float* features = (const float*)d_in[1];
    const float* rn       = (const float*)d_in[2];
    const float* gt       = (const float*)d_in[3];
    const int*   pred     = (const int*)d_in[4];   // int32
    const float* W1 = (const float*)d_in[5];
    const float* g1 = (const float*)d_in[7];
    const float* be1 = (const float*)d_in[8];
    const float* W2 = (const float*)d_in[9];
    const float* g2 = (const float*)d_in[11];
    const float* be2 = (const float*)d_in[12];
    const float* W3 = (const float*)d_in[13];
    const float* b3 = (const float*)d_in[14];
    const float* ms = (const float*)d_in[15];
    float* out = (float*)d_out;

    const int OFF_IDX = B_ * K_ * OCH;
    const int OFF_SUM = OFF_IDX + B_ * K_;
    const int OFF_LBL = OFF_SUM + B_;

    float *p_net1, *p_net2, *p_s, *p_s2;
    __half *p_W1h, *p_W2h, *p_W3h;
    cudaGetSymbolAddress((void**)&p_net1, g_net1);
    cudaGetSymbolAddress((void**)&p_net2, g_net2);
    cudaGetSymbolAddress((void**)&p_s,    g_s);
    cudaGetSymbolAddress((void**)&p_s2,   g_s2);
    cudaGetSymbolAddress((void**)&p_W1h,  g_W1h);
    cudaGetSymbolAddress((void**)&p_W2h,  g_W2h);
    cudaGetSymbolAddress((void**)&p_W3h,  g_W3h);

    prep_kernel<<<B_, K_>>>(xyz, gt, pred, W1, W2, W3,
                            out + OFF_LBL, out + OFF_IDX, out + OFF_SUM);

    dim3 gg(2, B_);
    // layer 1: concat input, stats -> g_s[0]
    wmma_gemm<256, 0, 1, 0><<<gg, 256>>>(p_W1h, nullptr, features, rn,
                                         nullptr, nullptr, nullptr, nullptr,
                                         p_net1, p_s, p_s2,
                                         nullptr, nullptr);
    // layer 2: in-kernel finalize from g_s[0], stats -> g_s[1]
    wmma_gemm<128, 1, 1, 0><<<gg, 256>>>(p_W2h, nullptr, p_net1, nullptr,
                                         g1, be1, p_s, p_s2,
                                         p_net2, p_s + C_, p_s2 + C_,
                                         nullptr, nullptr);
    // layer 3: in-kernel finalize from g_s[1], fused output assembly
    wmma_gemm<128, 1, 0, 1><<<gg, 256>>>(p_W3h, b3, p_net2, nullptr,
                                         g2, be2, p_s + C_, p_s2 + C_,
                                         out, nullptr, nullptr,
                                         xyz, ms);
}